// round 7
// baseline (speedup 1.0000x reference)
#include <cuda_runtime.h>

#define FULLMASK 0xffffffffu
#define IH 256
#define IW 192

typedef unsigned long long u64;

// Gaussian taps for kernel_size=11, sigma=10/6, normalized. Indexed by |d|.
static __device__ __forceinline__ float wt(int k) {
    const float t[6] = {0.23955940f, 0.20009682f, 0.11660614f,
                        0.04740849f, 0.01344761f, 0.00266126f};
    return t[k];
}

// Packed (lo=hi=tap) weights in constant memory: warp-uniform -> UR/LDCU path,
// frees 12 regular registers vs keeping them in the RF.
__constant__ u64 cw2[6] = {
    0x3e7554e73e7554e7ull,  // 0.23955940
    0x3e4ce5ca3e4ce5caull,  // 0.20009682
    0x3deecb8f3deecb8full,  // 0.11660614
    0x3d4229cb3d4229cbull,  // 0.04740849
    0x3c5c53f53c5c53f5ull,  // 0.01344761
    0x3b2e75293b2e7529ull   // 0.00266126
};

static __device__ __forceinline__ u64 pk(float lo, float hi) {
    u64 r; asm("mov.b64 %0, {%1, %2};" : "=l"(r) : "f"(lo), "f"(hi)); return r;
}
static __device__ __forceinline__ void upk(u64 v, float& lo, float& hi) {
    asm("mov.b64 {%0, %1}, %2;" : "=f"(lo), "=f"(hi) : "l"(v));
}
static __device__ __forceinline__ u64 f2mul(u64 a, u64 b) {
    u64 d; asm("mul.rn.f32x2 %0, %1, %2;" : "=l"(d) : "l"(a), "l"(b)); return d;
}
static __device__ __forceinline__ u64 f2fma(u64 a, u64 b, u64 c) {
    u64 d; asm("fma.rn.f32x2 %0, %1, %2, %3;" : "=l"(d) : "l"(a), "l"(b), "l"(c)); return d;
}
static __device__ __forceinline__ u64 f2add(u64 a, u64 b) {
    u64 d; asm("add.rn.f32x2 %0, %1, %2;" : "=l"(d) : "l"(a), "l"(b)); return d;
}

// One step of the fused blur/argmax pipeline (prefetch distance 1).
//  U      : static slot phase (i mod 11)
//  GUARD  : head/tail mode — runtime row/load bounds checks (warp-uniform)
//  EMIT   : emit completed output row (slot U) into the running argmax
// cur holds row r; this step consumes it and loads row r+1 into cur.
template<int U, bool GUARD, bool EMIT>
static __device__ __forceinline__ void step(
    const float* __restrict__ rp,   // main-mode load base: row of U=0 load
    const float* __restrict__ ip,   // image base (GUARD-mode addressing)
    int r, int col0,
    float (&cur)[6], u64 (&acc)[11][3],
    bool l0, bool l31, float& bestv, int& bestlin, int ebl)
{
    // ---- load row r+1 ----
    float nc[6];
    bool loadok = true, rowok = true;
    if (GUARD) {
        loadok = ((unsigned)(r + 1) < (unsigned)IH);
        rowok  = ((unsigned)r       < (unsigned)IH);
    }
    if (loadok) {
        const float* p = GUARD ? (ip + (r + 1) * IW + col0) : (rp + U * IW);
        float2 a = *(const float2*)p;
        float2 b = *(const float2*)(p + 2);
        float2 c = *(const float2*)(p + 4);
        nc[0] = a.x; nc[1] = a.y; nc[2] = b.x;
        nc[3] = b.y; nc[4] = c.x; nc[5] = c.y;
    } else {
        nc[0] = nc[1] = nc[2] = nc[3] = nc[4] = nc[5] = 0.f;
    }

    if (rowok) {
        // halos: lo = cols col0-5..col0-1, hi = cols col0+6..col0+10
        float hl[5], hh[5];
        hl[0] = __shfl_up_sync(FULLMASK, cur[1], 1);
        hl[1] = __shfl_up_sync(FULLMASK, cur[2], 1);
        hl[2] = __shfl_up_sync(FULLMASK, cur[3], 1);
        hl[3] = __shfl_up_sync(FULLMASK, cur[4], 1);
        hl[4] = __shfl_up_sync(FULLMASK, cur[5], 1);
        hh[0] = __shfl_down_sync(FULLMASK, cur[0], 1);
        hh[1] = __shfl_down_sync(FULLMASK, cur[1], 1);
        hh[2] = __shfl_down_sync(FULLMASK, cur[2], 1);
        hh[3] = __shfl_down_sync(FULLMASK, cur[3], 1);
        hh[4] = __shfl_down_sync(FULLMASK, cur[4], 1);
        if (l0)  { hl[0]=0.f; hl[1]=0.f; hl[2]=0.f; hl[3]=0.f; hl[4]=0.f; }
        if (l31) { hh[0]=0.f; hh[1]=0.f; hh[2]=0.f; hh[3]=0.f; hh[4]=0.f; }

        // adjacent pairs over extended segment e[0..15]
        u64 P[15];
        P[0]  = pk(hl[0], hl[1]);
        P[1]  = pk(hl[1], hl[2]);
        P[2]  = pk(hl[2], hl[3]);
        P[3]  = pk(hl[3], hl[4]);
        P[4]  = pk(hl[4], cur[0]);
        P[5]  = pk(cur[0], cur[1]);
        P[6]  = pk(cur[1], cur[2]);
        P[7]  = pk(cur[2], cur[3]);
        P[8]  = pk(cur[3], cur[4]);
        P[9]  = pk(cur[4], cur[5]);
        P[10] = pk(cur[5], hh[0]);
        P[11] = pk(hh[0], hh[1]);
        P[12] = pk(hh[1], hh[2]);
        P[13] = pk(hh[2], hh[3]);
        P[14] = pk(hh[3], hh[4]);

        // horizontal blur (packed, even/odd split chains)
        u64 h2[3];
#pragma unroll
        for (int j = 0; j < 3; ++j) {
            u64 sa = f2mul(P[2*j + 0], cw2[5]);
            sa = f2fma(P[2*j + 2],  cw2[3], sa);
            sa = f2fma(P[2*j + 4],  cw2[1], sa);
            sa = f2fma(P[2*j + 6],  cw2[1], sa);
            sa = f2fma(P[2*j + 8],  cw2[3], sa);
            sa = f2fma(P[2*j + 10], cw2[5], sa);
            u64 sb = f2mul(P[2*j + 1], cw2[4]);
            sb = f2fma(P[2*j + 3],  cw2[2], sb);
            sb = f2fma(P[2*j + 5],  cw2[0], sb);
            sb = f2fma(P[2*j + 7],  cw2[2], sb);
            sb = f2fma(P[2*j + 9],  cw2[4], sb);
            h2[j] = f2add(sa, sb);
        }

        // vertical taps: k=0..9 accumulate, k=10 overwrites recycled slot
#pragma unroll
        for (int k = 0; k < 10; ++k) {
            const u64 wv = cw2[k <= 5 ? 5 - k : k - 5];
            const int s = (U + k) % 11;
            acc[s][0] = f2fma(h2[0], wv, acc[s][0]);
            acc[s][1] = f2fma(h2[1], wv, acc[s][1]);
            acc[s][2] = f2fma(h2[2], wv, acc[s][2]);
        }
        {
            const int s = (U + 10) % 11;
            acc[s][0] = f2mul(h2[0], cw2[5]);
            acc[s][1] = f2mul(h2[1], cw2[5]);
            acc[s][2] = f2mul(h2[2], cw2[5]);
        }
    } else {
        const int s = (U + 10) % 11;
        acc[s][0] = 0ull; acc[s][1] = 0ull; acc[s][2] = 0ull;
    }

    if (EMIT) {
        float a0, a1, a2, a3, a4, a5;
        upk(acc[U][0], a0, a1);
        upk(acc[U][1], a2, a3);
        upk(acc[U][2], a4, a5);
        const float m01 = fmaxf(a0, a1);
        const float m23 = fmaxf(a2, a3);
        const float m45 = fmaxf(a4, a5);
        const float rowmax = fmaxf(fmaxf(m01, m23), m45);
        if (rowmax > bestv) {           // rare
            bestv = rowmax;
            int c = 5;
            if (a4 == rowmax) c = 4;
            if (a3 == rowmax) c = 3;
            if (a2 == rowmax) c = 2;
            if (a1 == rowmax) c = 1;
            if (a0 == rowmax) c = 0;
            bestlin = ebl + U * IW + c;
        }
    }

#pragma unroll
    for (int c = 0; c < 6; ++c) cur[c] = nc[c];
}

// One CTA (128 threads = 4 warps) per (b,k) image; warp w owns output rows
// [w*64, w*64+64), lane owns 6 columns. 74 steps per warp:
// head 11 guarded + main 5x11 branch-free + tail 8 guarded.
__global__ __launch_bounds__(128, 5)
void dark_decode_kernel(const float* __restrict__ hm,
                        float* __restrict__ out, int n_img)
{
    const int img  = blockIdx.x;
    const int warp = threadIdx.x >> 5;
    const int lane = threadIdx.x & 31;
    const float* __restrict__ ip = hm + (long long)img * (IH * IW);
    const int base = warp * 64;          // output rows [base, base+64)
    const int col0 = lane * 6;
    const bool l0  = (lane == 0);
    const bool l31 = (lane == 31);

    u64 acc[11][3];   // no init needed: every slot is overwritten before emit

    float cur[6];
    {   // row base-5 (warp 0: OOB -> zeros)
        const int r0 = base - 5;
        if (r0 >= 0) {
            const float* p = ip + r0 * IW + col0;
            float2 a = *(const float2*)p;
            float2 b = *(const float2*)(p + 2);
            float2 c = *(const float2*)(p + 4);
            cur[0]=a.x; cur[1]=a.y; cur[2]=b.x; cur[3]=b.y; cur[4]=c.x; cur[5]=c.y;
        } else {
#pragma unroll
            for (int c = 0; c < 6; ++c) cur[c] = 0.f;
        }
    }

    float bestv   = -3.4e38f;
    int   bestlin = 0;

    // ---- head: i = 0..10 (r = base-5+i), guarded; emit only at i=10 ----
    {
        const int eblh = (base - 10) * IW + col0;
#define HSTEP(U, EM) step<U, true, EM>(ip, ip, base - 5 + (U), col0, cur, acc, \
                                       l0, l31, bestv, bestlin, eblh)
        HSTEP(0, false); HSTEP(1, false); HSTEP(2, false); HSTEP(3, false);
        HSTEP(4, false); HSTEP(5, false); HSTEP(6, false); HSTEP(7, false);
        HSTEP(8, false); HSTEP(9, false); HSTEP(10, true);
#undef HSTEP
    }

    // ---- main: i = 11..65, 5 blocks x 11 steps, branch-free ----
    // step i loads row base-4+i; max = base+61 <= 253 -> always in bounds.
    {
        const float* rp = ip + (base + 7) * IW + col0;   // row of U=0 load, blk 0
        int ebl = (base + 1) * IW + col0;                // ro at blk=0,U=0
#define MSTEP(U) step<U, false, true>(rp, ip, 0, col0, cur, acc, l0, l31, \
                                      bestv, bestlin, ebl)
        for (int blk = 0; blk < 5; ++blk) {
            MSTEP(0); MSTEP(1); MSTEP(2); MSTEP(3); MSTEP(4); MSTEP(5);
            MSTEP(6); MSTEP(7); MSTEP(8); MSTEP(9); MSTEP(10);
            rp  += 11 * IW;
            ebl += 11 * IW;
        }
#undef MSTEP
    }

    // ---- tail: i = 66..73 (U = 0..7, r = base+61+U), guarded, always emit ----
    {
        const int eblt = (base + 56) * IW + col0;
#define TSTEP(U) step<U, true, true>(ip, ip, base + 61 + (U), col0, cur, acc, \
                                     l0, l31, bestv, bestlin, eblt)
        TSTEP(0); TSTEP(1); TSTEP(2); TSTEP(3);
        TSTEP(4); TSTEP(5); TSTEP(6); TSTEP(7);
#undef TSTEP
    }

    // intra-warp argmax reduce (larger value wins; tie -> smaller linear index)
#pragma unroll
    for (int off = 16; off >= 1; off >>= 1) {
        const float ov = __shfl_xor_sync(FULLMASK, bestv, off);
        const int   oi = __shfl_xor_sync(FULLMASK, bestlin, off);
        if (ov > bestv || (ov == bestv && oi < bestlin)) { bestv = ov; bestlin = oi; }
    }

    __shared__ float s_v[4];
    __shared__ int   s_i[4];
    if (lane == 0) { s_v[warp] = bestv; s_i[warp] = bestlin; }
    __syncthreads();
    if (warp != 0) return;

    float fv = s_v[0]; int fl = s_i[0];
#pragma unroll
    for (int w = 1; w < 4; ++w) {
        const float vw = s_v[w]; const int iw = s_i[w];
        if (vw > fv || (vw == fv && iw < fl)) { fv = vw; fl = iw; }
    }
    const int py = fl / IW;
    const int px = fl - py * IW;

    float offx = 0.f, offy = 0.f;
    const bool bok = (px >= 1) && (px < IW - 1) && (py >= 1) && (py < IH - 1);
    if (bok) {
        // 39 hblur values: flat j in [0,39), rr = py-6 + j/3, cc = px-1 + j%3
        float h0 = 0.f, h1 = 0.f;
        {
            int j = lane;
            int rr = py - 6 + j / 3;
            int cc = px - 1 + (j - (j / 3) * 3);
            if (rr >= 0 && rr < IH) {
                const float* rp2 = ip + rr * IW;
                float s = 0.f;
#pragma unroll
                for (int d = -5; d <= 5; ++d) {
                    const int c = cc + d;
                    float v = 0.f;
                    if ((unsigned)c < (unsigned)IW) v = rp2[c];
                    s += v * wt(d < 0 ? -d : d);
                }
                h0 = s;
            }
            j = lane + 32;
            if (j < 39) {
                rr = py - 6 + j / 3;
                cc = px - 1 + (j - (j / 3) * 3);
                if (rr >= 0 && rr < IH) {
                    const float* rp2 = ip + rr * IW;
                    float s = 0.f;
#pragma unroll
                    for (int d = -5; d <= 5; ++d) {
                        const int c = cc + d;
                        float v = 0.f;
                        if ((unsigned)c < (unsigned)IW) v = rp2[c];
                        s += v * wt(d < 0 ? -d : d);
                    }
                    h1 = s;
                }
            }
        }
        // lanes 0..8: vertical blur -> patch entry p(a,b), a=lane/3, b=lane%3
        const int a = lane / 3;
        const int b = lane - a * 3;
        float p = 0.f;
#pragma unroll
        for (int t = 0; t < 11; ++t) {
            const int j = (a + t) * 3 + b;
            const float va = __shfl_sync(FULLMASK, h0, j & 31);
            const float vb = __shfl_sync(FULLMASK, h1, j & 31);
            const float hv = (j < 32) ? va : vb;
            p += hv * wt(t <= 5 ? 5 - t : t - 5);
        }
        const float p00 = __shfl_sync(FULLMASK, p, 0);
        const float p01 = __shfl_sync(FULLMASK, p, 1);
        const float p02 = __shfl_sync(FULLMASK, p, 2);
        const float p10 = __shfl_sync(FULLMASK, p, 3);
        const float p11 = __shfl_sync(FULLMASK, p, 4);
        const float p12 = __shfl_sync(FULLMASK, p, 5);
        const float p20 = __shfl_sync(FULLMASK, p, 6);
        const float p21 = __shfl_sync(FULLMASK, p, 7);
        const float p22 = __shfl_sync(FULLMASK, p, 8);

        const float dx  = (p12 - p10) * 0.5f;
        const float dy  = (p21 - p01) * 0.5f;
        const float dxx = p12 - 2.f * p11 + p10;
        const float dyy = p21 - 2.f * p11 + p01;
        const float dxy = (p22 - p20 - p02 + p00) * 0.25f;
        const float det = dxx * dyy - dxy * dxy;
        if (fabsf(det) >= 1e-6f && dxx < 0.f) {
            const float ox = -(dyy * dx - dxy * dy) / det;
            const float oy = -(dxx * dy - dxy * dx) / det;
            offx = fminf(fmaxf(ox, -0.5f), 0.5f);
            offy = fminf(fmaxf(oy, -0.5f), 0.5f);
        }
    }

    if (lane == 0) {
        const float xo = fminf(fmaxf((float)px + offx, 0.f), (float)(IW - 1));
        const float yo = fminf(fmaxf((float)py + offy, 0.f), (float)(IH - 1));
        out[2 * img + 0] = xo;                       // coords[...,0] = x
        out[2 * img + 1] = yo;                       // coords[...,1] = y
        out[(long long)2 * n_img + img] = fv;        // max_vals
    }
}

extern "C" void kernel_launch(void* const* d_in, const int* in_sizes, int n_in,
                              void* d_out, int out_size)
{
    const float* hm = (const float*)d_in[0];
    // d_in[1] is kernel_size (always 11 in this problem; taps are baked in)
    const int n_img = in_sizes[0] / (IH * IW);
    dark_decode_kernel<<<n_img, 128>>>(hm, (float*)d_out, n_img);
}

// round 8
// speedup vs baseline: 1.1047x; 1.1047x over previous
#include <cuda_runtime.h>

#define FULLMASK 0xffffffffu
#define IH 256
#define IW 192

typedef unsigned long long u64;

// Gaussian taps for kernel_size=11, sigma=10/6, normalized. Indexed by |d|.
static __device__ __forceinline__ float wt(int k) {
    const float t[6] = {0.23955940f, 0.20009682f, 0.11660614f,
                        0.04740849f, 0.01344761f, 0.00266126f};
    return t[k];
}

// Packed (lo=hi=tap) weights in constant memory, compiler-encoded (no hand
// hex!). Warp-uniform -> LDCU/UR path, frees ~12 u64 registers.
__constant__ float2 cw2f[6] = {
    {0.23955940f, 0.23955940f},
    {0.20009682f, 0.20009682f},
    {0.11660614f, 0.11660614f},
    {0.04740849f, 0.04740849f},
    {0.01344761f, 0.01344761f},
    {0.00266126f, 0.00266126f}
};
#define CW2(k) (reinterpret_cast<const u64*>(cw2f)[k])

static __device__ __forceinline__ u64 pk(float lo, float hi) {
    u64 r; asm("mov.b64 %0, {%1, %2};" : "=l"(r) : "f"(lo), "f"(hi)); return r;
}
static __device__ __forceinline__ void upk(u64 v, float& lo, float& hi) {
    asm("mov.b64 {%0, %1}, %2;" : "=f"(lo), "=f"(hi) : "l"(v));
}
static __device__ __forceinline__ u64 f2mul(u64 a, u64 b) {
    u64 d; asm("mul.rn.f32x2 %0, %1, %2;" : "=l"(d) : "l"(a), "l"(b)); return d;
}
static __device__ __forceinline__ u64 f2fma(u64 a, u64 b, u64 c) {
    u64 d; asm("fma.rn.f32x2 %0, %1, %2, %3;" : "=l"(d) : "l"(a), "l"(b), "l"(c)); return d;
}
static __device__ __forceinline__ u64 f2add(u64 a, u64 b) {
    u64 d; asm("add.rn.f32x2 %0, %1, %2;" : "=l"(d) : "l"(a), "l"(b)); return d;
}

// One step of the fused blur/argmax pipeline (prefetch distance 1).
//  U      : static slot phase (i mod 11)
//  GUARD  : head/tail mode — runtime row/load bounds checks (warp-uniform)
//  EMIT   : fold completed output row (slot U) into branchless running max
// cur holds row r; this step consumes it and loads row r+1 into cur.
template<int U, bool GUARD, bool EMIT>
static __device__ __forceinline__ void step(
    const float* __restrict__ rp,   // main-mode load base: row of U=0 load
    const float* __restrict__ ip,   // image base (GUARD-mode addressing)
    int r, int col0,
    float (&cur)[6], u64 (&acc)[11][3],
    bool l0, bool l31, float& bestv, int& bestrow, int ebl)
{
    // ---- load row r+1 ----
    float nc[6];
    bool loadok = true, rowok = true;
    if (GUARD) {
        loadok = ((unsigned)(r + 1) < (unsigned)IH);
        rowok  = ((unsigned)r       < (unsigned)IH);
    }
    if (loadok) {
        const float* p = GUARD ? (ip + (r + 1) * IW + col0) : (rp + U * IW);
        float2 a = *(const float2*)p;
        float2 b = *(const float2*)(p + 2);
        float2 c = *(const float2*)(p + 4);
        nc[0] = a.x; nc[1] = a.y; nc[2] = b.x;
        nc[3] = b.y; nc[4] = c.x; nc[5] = c.y;
    } else {
        nc[0] = nc[1] = nc[2] = nc[3] = nc[4] = nc[5] = 0.f;
    }

    if (rowok) {
        // halos: lo = cols col0-5..col0-1, hi = cols col0+6..col0+10
        float hl[5], hh[5];
        hl[0] = __shfl_up_sync(FULLMASK, cur[1], 1);
        hl[1] = __shfl_up_sync(FULLMASK, cur[2], 1);
        hl[2] = __shfl_up_sync(FULLMASK, cur[3], 1);
        hl[3] = __shfl_up_sync(FULLMASK, cur[4], 1);
        hl[4] = __shfl_up_sync(FULLMASK, cur[5], 1);
        hh[0] = __shfl_down_sync(FULLMASK, cur[0], 1);
        hh[1] = __shfl_down_sync(FULLMASK, cur[1], 1);
        hh[2] = __shfl_down_sync(FULLMASK, cur[2], 1);
        hh[3] = __shfl_down_sync(FULLMASK, cur[3], 1);
        hh[4] = __shfl_down_sync(FULLMASK, cur[4], 1);
        if (l0)  { hl[0]=0.f; hl[1]=0.f; hl[2]=0.f; hl[3]=0.f; hl[4]=0.f; }
        if (l31) { hh[0]=0.f; hh[1]=0.f; hh[2]=0.f; hh[3]=0.f; hh[4]=0.f; }

        // adjacent pairs over extended segment e[0..15]
        u64 P[15];
        P[0]  = pk(hl[0], hl[1]);
        P[1]  = pk(hl[1], hl[2]);
        P[2]  = pk(hl[2], hl[3]);
        P[3]  = pk(hl[3], hl[4]);
        P[4]  = pk(hl[4], cur[0]);
        P[5]  = pk(cur[0], cur[1]);
        P[6]  = pk(cur[1], cur[2]);
        P[7]  = pk(cur[2], cur[3]);
        P[8]  = pk(cur[3], cur[4]);
        P[9]  = pk(cur[4], cur[5]);
        P[10] = pk(cur[5], hh[0]);
        P[11] = pk(hh[0], hh[1]);
        P[12] = pk(hh[1], hh[2]);
        P[13] = pk(hh[2], hh[3]);
        P[14] = pk(hh[3], hh[4]);

        // horizontal blur (packed, even/odd split chains)
        u64 h2[3];
#pragma unroll
        for (int j = 0; j < 3; ++j) {
            u64 sa = f2mul(P[2*j + 0], CW2(5));
            sa = f2fma(P[2*j + 2],  CW2(3), sa);
            sa = f2fma(P[2*j + 4],  CW2(1), sa);
            sa = f2fma(P[2*j + 6],  CW2(1), sa);
            sa = f2fma(P[2*j + 8],  CW2(3), sa);
            sa = f2fma(P[2*j + 10], CW2(5), sa);
            u64 sb = f2mul(P[2*j + 1], CW2(4));
            sb = f2fma(P[2*j + 3],  CW2(2), sb);
            sb = f2fma(P[2*j + 5],  CW2(0), sb);
            sb = f2fma(P[2*j + 7],  CW2(2), sb);
            sb = f2fma(P[2*j + 9],  CW2(4), sb);
            h2[j] = f2add(sa, sb);
        }

        // vertical taps: k=0..9 accumulate, k=10 overwrites recycled slot
#pragma unroll
        for (int k = 0; k < 10; ++k) {
            const u64 wv = CW2(k <= 5 ? 5 - k : k - 5);
            const int s = (U + k) % 11;
            acc[s][0] = f2fma(h2[0], wv, acc[s][0]);
            acc[s][1] = f2fma(h2[1], wv, acc[s][1]);
            acc[s][2] = f2fma(h2[2], wv, acc[s][2]);
        }
        {
            const int s = (U + 10) % 11;
            acc[s][0] = f2mul(h2[0], CW2(5));
            acc[s][1] = f2mul(h2[1], CW2(5));
            acc[s][2] = f2mul(h2[2], CW2(5));
        }
    } else {
        const int s = (U + 10) % 11;
        acc[s][0] = 0ull; acc[s][1] = 0ull; acc[s][2] = 0ull;
    }

    if (EMIT) {
        float a0, a1, a2, a3, a4, a5;
        upk(acc[U][0], a0, a1);
        upk(acc[U][1], a2, a3);
        upk(acc[U][2], a4, a5);
        const float m01 = fmaxf(a0, a1);
        const float m23 = fmaxf(a2, a3);
        const float m45 = fmaxf(a4, a5);
        const float rowmax = fmaxf(fmaxf(m01, m23), m45);
        // branchless: keep (max value, earliest row-base on strict improvement)
        const int rowbase = ebl + U * IW;        // ro*IW + col0
        bestrow = (rowmax > bestv) ? rowbase : bestrow;
        bestv   = fmaxf(bestv, rowmax);
    }

#pragma unroll
    for (int c = 0; c < 6; ++c) cur[c] = nc[c];
}

// One CTA (64 threads = 2 warps) per (b,k) image; warp w owns output rows
// [w*128, w*128+128), lane owns 6 columns. Head (11 guarded) + main
// (11x11 branch-free) + tail (6 guarded).
__global__ __launch_bounds__(64, 8)
void dark_decode_kernel(const float* __restrict__ hm,
                        float* __restrict__ out, int n_img)
{
    const int img  = blockIdx.x;
    const int warp = threadIdx.x >> 5;
    const int lane = threadIdx.x & 31;
    const float* __restrict__ ip = hm + (long long)img * (IH * IW);
    const int base = warp * 128;
    const int col0 = lane * 6;
    const bool l0  = (lane == 0);
    const bool l31 = (lane == 31);

    u64 acc[11][3];   // no init needed: every slot is overwritten before emit

    float cur[6];
    {   // row base-5 (warp0: OOB -> zeros)
        const int r0 = base - 5;
        if (r0 >= 0) {
            const float* p = ip + r0 * IW + col0;
            float2 a = *(const float2*)p;
            float2 b = *(const float2*)(p + 2);
            float2 c = *(const float2*)(p + 4);
            cur[0]=a.x; cur[1]=a.y; cur[2]=b.x; cur[3]=b.y; cur[4]=c.x; cur[5]=c.y;
        } else {
#pragma unroll
            for (int c = 0; c < 6; ++c) cur[c] = 0.f;
        }
    }

    float bestv   = -3.4e38f;
    int   bestrow = 0;

    // ---- head: i = 0..10 (r = base-5+i), guarded; emit only at i=10 ----
    {
        const int eblh = (base - 10) * IW + col0;
#define HSTEP(U, EM) step<U, true, EM>(ip, ip, base - 5 + (U), col0, cur, acc, \
                                       l0, l31, bestv, bestrow, eblh)
        HSTEP(0, false); HSTEP(1, false); HSTEP(2, false); HSTEP(3, false);
        HSTEP(4, false); HSTEP(5, false); HSTEP(6, false); HSTEP(7, false);
        HSTEP(8, false); HSTEP(9, false); HSTEP(10, true);
#undef HSTEP
    }

    // ---- main: i = 11..131, 11 blocks x 11 steps, branch-free ----
    {
        const float* rp = ip + (base + 7) * IW + col0;   // row r+1 at ib=0,U=0
        int ebl = (base + 1) * IW + col0;                // ro at ib=0,U=0
#define MSTEP(U) step<U, false, true>(rp, ip, 0, col0, cur, acc, l0, l31, \
                                      bestv, bestrow, ebl)
        for (int ib = 0; ib < 11; ++ib) {
            MSTEP(0); MSTEP(1); MSTEP(2); MSTEP(3); MSTEP(4); MSTEP(5);
            MSTEP(6); MSTEP(7); MSTEP(8); MSTEP(9); MSTEP(10);
            rp  += 11 * IW;
            ebl += 11 * IW;
        }
#undef MSTEP
    }

    // ---- tail: i = 132..137 (U = 0..5), guarded, always emit ----
    {
        const int eblt = (base + 122) * IW + col0;
#define TSTEP(U) step<U, true, true>(ip, ip, base + 127 + (U), col0, cur, acc, \
                                     l0, l31, bestv, bestrow, eblt)
        TSTEP(0); TSTEP(1); TSTEP(2); TSTEP(3); TSTEP(4); TSTEP(5);
#undef TSTEP
    }

    // intra-warp argmax reduce (larger value wins; tie -> smaller row-base)
#pragma unroll
    for (int off = 16; off >= 1; off >>= 1) {
        const float ov = __shfl_xor_sync(FULLMASK, bestv, off);
        const int   oi = __shfl_xor_sync(FULLMASK, bestrow, off);
        if (ov > bestv || (ov == bestv && oi < bestrow)) { bestv = ov; bestrow = oi; }
    }

    __shared__ float s_v[2];
    __shared__ int   s_i[2];
    if (lane == 0) { s_v[warp] = bestv; s_i[warp] = bestrow; }
    __syncthreads();
    if (warp != 0) return;

    float fv; int fl;
    {
        const float v0 = s_v[0], v1 = s_v[1];
        const int   i0 = s_i[0], i1 = s_i[1];
        if (v1 > v0 || (v1 == v0 && i1 < i0)) { fv = v1; fl = i1; }
        else                                  { fv = v0; fl = i0; }
    }
    const int py  = fl / IW;
    const int c0w = fl - py * IW;     // winning lane's col0

    // ---- column recovery: lanes 0..5 recompute blurred(py, c0w+lane)
    // bitwise-identically to the streaming accumulation (same chains/order).
    float val = -3.4e38f;
    if (lane < 6) {
        const int cc = c0w + lane;
        val = 0.f;
#pragma unroll
        for (int t = 0; t < 11; ++t) {
            const int r = py - 5 + t;
            if (r >= 0 && r < IH) {
                const float* rp2 = ip + r * IW;
                float x[11];
#pragma unroll
                for (int d = -5; d <= 5; ++d) {
                    const int c = cc + d;
                    x[d + 5] = ((unsigned)c < (unsigned)IW) ? rp2[c] : 0.f;
                }
                float sa = x[0] * wt(5);          // dist -5
                sa = fmaf(x[2],  wt(3), sa);      // -3
                sa = fmaf(x[4],  wt(1), sa);      // -1
                sa = fmaf(x[6],  wt(1), sa);      // +1
                sa = fmaf(x[8],  wt(3), sa);      // +3
                sa = fmaf(x[10], wt(5), sa);      // +5
                float sb = x[1] * wt(4);          // -4
                sb = fmaf(x[3], wt(2), sb);       // -2
                sb = fmaf(x[5], wt(0), sb);       //  0
                sb = fmaf(x[7], wt(2), sb);       // +2
                sb = fmaf(x[9], wt(4), sb);       // +4
                const float h = sa + sb;
                val = fmaf(h, wt(t < 5 ? 5 - t : t - 5), val);
            }
        }
    }
    // first-max among lanes 0..5 (8-lane bfly max + ballot + ffs)
    float mx = val;
    mx = fmaxf(mx, __shfl_xor_sync(FULLMASK, mx, 1));
    mx = fmaxf(mx, __shfl_xor_sync(FULLMASK, mx, 2));
    mx = fmaxf(mx, __shfl_xor_sync(FULLMASK, mx, 4));
    const unsigned bal = __ballot_sync(FULLMASK, (lane < 6) && (val == mx));
    const int cwin = __ffs(bal) - 1;
    const int px = c0w + cwin;

    float offx = 0.f, offy = 0.f;
    const bool bok = (px >= 1) && (px < IW - 1) && (py >= 1) && (py < IH - 1);
    if (bok) {
        // 39 hblur values: flat j in [0,39), rr = py-6 + j/3, cc = px-1 + j%3
        float h0 = 0.f, h1 = 0.f;
        {
            int j = lane;
            int rr = py - 6 + j / 3;
            int cc = px - 1 + (j - (j / 3) * 3);
            if (rr >= 0 && rr < IH) {
                const float* rp2 = ip + rr * IW;
                float s = 0.f;
#pragma unroll
                for (int d = -5; d <= 5; ++d) {
                    const int c = cc + d;
                    float v = 0.f;
                    if ((unsigned)c < (unsigned)IW) v = rp2[c];
                    s += v * wt(d < 0 ? -d : d);
                }
                h0 = s;
            }
            j = lane + 32;
            if (j < 39) {
                rr = py - 6 + j / 3;
                cc = px - 1 + (j - (j / 3) * 3);
                if (rr >= 0 && rr < IH) {
                    const float* rp2 = ip + rr * IW;
                    float s = 0.f;
#pragma unroll
                    for (int d = -5; d <= 5; ++d) {
                        const int c = cc + d;
                        float v = 0.f;
                        if ((unsigned)c < (unsigned)IW) v = rp2[c];
                        s += v * wt(d < 0 ? -d : d);
                    }
                    h1 = s;
                }
            }
        }
        // lanes 0..8: vertical blur -> patch entry p(a,b), a=lane/3, b=lane%3
        const int a = lane / 3;
        const int b = lane - a * 3;
        float p = 0.f;
#pragma unroll
        for (int t = 0; t < 11; ++t) {
            const int j = (a + t) * 3 + b;
            const float va = __shfl_sync(FULLMASK, h0, j & 31);
            const float vb = __shfl_sync(FULLMASK, h1, j & 31);
            const float hv = (j < 32) ? va : vb;
            p += hv * wt(t <= 5 ? 5 - t : t - 5);
        }
        const float p00 = __shfl_sync(FULLMASK, p, 0);
        const float p01 = __shfl_sync(FULLMASK, p, 1);
        const float p02 = __shfl_sync(FULLMASK, p, 2);
        const float p10 = __shfl_sync(FULLMASK, p, 3);
        const float p11 = __shfl_sync(FULLMASK, p, 4);
        const float p12 = __shfl_sync(FULLMASK, p, 5);
        const float p20 = __shfl_sync(FULLMASK, p, 6);
        const float p21 = __shfl_sync(FULLMASK, p, 7);
        const float p22 = __shfl_sync(FULLMASK, p, 8);

        const float dx  = (p12 - p10) * 0.5f;
        const float dy  = (p21 - p01) * 0.5f;
        const float dxx = p12 - 2.f * p11 + p10;
        const float dyy = p21 - 2.f * p11 + p01;
        const float dxy = (p22 - p20 - p02 + p00) * 0.25f;
        const float det = dxx * dyy - dxy * dxy;
        if (fabsf(det) >= 1e-6f && dxx < 0.f) {
            const float ox = -(dyy * dx - dxy * dy) / det;
            const float oy = -(dxx * dy - dxy * dx) / det;
            offx = fminf(fmaxf(ox, -0.5f), 0.5f);
            offy = fminf(fmaxf(oy, -0.5f), 0.5f);
        }
    }

    if (lane == 0) {
        const float xo = fminf(fmaxf((float)px + offx, 0.f), (float)(IW - 1));
        const float yo = fminf(fmaxf((float)py + offy, 0.f), (float)(IH - 1));
        out[2 * img + 0] = xo;                       // coords[...,0] = x
        out[2 * img + 1] = yo;                       // coords[...,1] = y
        out[(long long)2 * n_img + img] = fv;        // max_vals
    }
}

extern "C" void kernel_launch(void* const* d_in, const int* in_sizes, int n_in,
                              void* d_out, int out_size)
{
    const float* hm = (const float*)d_in[0];
    // d_in[1] is kernel_size (always 11 in this problem; taps are baked in)
    const int n_img = in_sizes[0] / (IH * IW);
    dark_decode_kernel<<<n_img, 64>>>(hm, (float*)d_out, n_img);
}

// round 9
// speedup vs baseline: 1.1987x; 1.0850x over previous
#include <cuda_runtime.h>

#define FULLMASK 0xffffffffu
#define IH 256
#define IW 192

typedef unsigned long long u64;
typedef unsigned int u32;

// Gaussian taps for kernel_size=11, sigma=10/6, normalized. Indexed by |d|.
static __device__ __forceinline__ float wt(int k) {
    const float t[6] = {0.23955940f, 0.20009682f, 0.11660614f,
                        0.04740849f, 0.01344761f, 0.00266126f};
    return t[k];
}

static __device__ __forceinline__ u64 pk(float lo, float hi) {
    u64 r; asm("mov.b64 %0, {%1, %2};" : "=l"(r) : "f"(lo), "f"(hi)); return r;
}
static __device__ __forceinline__ void upk(u64 v, float& lo, float& hi) {
    asm("mov.b64 {%0, %1}, %2;" : "=f"(lo), "=f"(hi) : "l"(v));
}
static __device__ __forceinline__ u64 f2mul(u64 a, u64 b) {
    u64 d; asm("mul.rn.f32x2 %0, %1, %2;" : "=l"(d) : "l"(a), "l"(b)); return d;
}
static __device__ __forceinline__ u64 f2fma(u64 a, u64 b, u64 c) {
    u64 d; asm("fma.rn.f32x2 %0, %1, %2, %3;" : "=l"(d) : "l"(a), "l"(b), "l"(c)); return d;
}
static __device__ __forceinline__ u64 f2add(u64 a, u64 b) {
    u64 d; asm("add.rn.f32x2 %0, %1, %2;" : "=l"(d) : "l"(a), "l"(b)); return d;
}

static __device__ __forceinline__ u32 smem_u32(const void* p) {
    u32 a;
    asm("{ .reg .u64 t; cvta.to.shared.u64 t, %1; cvt.u32.u64 %0, t; }"
        : "=r"(a) : "l"(p));
    return a;
}

#define CP_ASYNC8(dst, src) \
    asm volatile("cp.async.ca.shared.global [%0], [%1], 8;" \
                 :: "r"(dst), "l"(src) : "memory")
#define CP_COMMIT() asm volatile("cp.async.commit_group;" ::: "memory")
#define CP_WAIT(n)  asm volatile("cp.async.wait_group %0;" :: "n"(n) : "memory")

// One step of the fused blur/argmax pipeline.
//  U    : static slot phase (i mod 11)
//  SMEM : main mode — consume row from cp.async smem ring, prefetch row +6
//         (!SMEM = guarded direct-gmem mode for head/tail)
//  EMIT : emit completed output row (slot U) into the running argmax
//  PF   : (SMEM only) issue the 3-8B-prefetches for row +6
// cur holds row r; this step consumes it and loads row r+1 into cur.
template<int U, bool SMEM, bool EMIT, bool PF>
static __device__ __forceinline__ void step(
    const float* __restrict__ ip, int r, int col0,
    float (&cur)[6], u64 (&acc)[11][3], const u64 (&w2)[6],
    bool l0, bool l31, float& bestv, int& bestlin, int ebl,
    u32 sb, u32& wro, const float*& gp)
{
    // ---- acquire row r+1 ----
    float nc[6];
    bool rowok = true;
    if (SMEM) {
        CP_WAIT(5);   // row for this step's LDS is guaranteed resident
        const u32 rd = sb + ((wro + 2048u) & 8191u);   // read slot = write slot+2 (mod 8)
        asm volatile("ld.shared.v2.f32 {%0,%1},[%2];"
                     : "=f"(nc[0]), "=f"(nc[1]) : "r"(rd));
        asm volatile("ld.shared.v2.f32 {%0,%1},[%2];"
                     : "=f"(nc[2]), "=f"(nc[3]) : "r"(rd + 8u));
        asm volatile("ld.shared.v2.f32 {%0,%1},[%2];"
                     : "=f"(nc[4]), "=f"(nc[5]) : "r"(rd + 16u));
        if (PF) {
            const u32 wr = sb + wro;
            CP_ASYNC8(wr,        gp);
            CP_ASYNC8(wr + 8u,   gp + 2);
            CP_ASYNC8(wr + 16u,  gp + 4);
        }
        CP_COMMIT();                      // exactly one group per step
        wro = (wro + 1024u) & 8191u;
        gp += IW;
    } else {
        const bool loadok = ((unsigned)(r + 1) < (unsigned)IH);
        rowok = ((unsigned)r < (unsigned)IH);
        if (loadok) {
            const float* p = ip + (r + 1) * IW + col0;
            float2 a = *(const float2*)p;
            float2 b = *(const float2*)(p + 2);
            float2 c = *(const float2*)(p + 4);
            nc[0] = a.x; nc[1] = a.y; nc[2] = b.x;
            nc[3] = b.y; nc[4] = c.x; nc[5] = c.y;
        } else {
            nc[0] = nc[1] = nc[2] = nc[3] = nc[4] = nc[5] = 0.f;
        }
    }

    if (rowok) {
        // halos: lo = cols col0-5..col0-1, hi = cols col0+6..col0+10
        float hl[5], hh[5];
        hl[0] = __shfl_up_sync(FULLMASK, cur[1], 1);
        hl[1] = __shfl_up_sync(FULLMASK, cur[2], 1);
        hl[2] = __shfl_up_sync(FULLMASK, cur[3], 1);
        hl[3] = __shfl_up_sync(FULLMASK, cur[4], 1);
        hl[4] = __shfl_up_sync(FULLMASK, cur[5], 1);
        hh[0] = __shfl_down_sync(FULLMASK, cur[0], 1);
        hh[1] = __shfl_down_sync(FULLMASK, cur[1], 1);
        hh[2] = __shfl_down_sync(FULLMASK, cur[2], 1);
        hh[3] = __shfl_down_sync(FULLMASK, cur[3], 1);
        hh[4] = __shfl_down_sync(FULLMASK, cur[4], 1);
        if (l0)  { hl[0]=0.f; hl[1]=0.f; hl[2]=0.f; hl[3]=0.f; hl[4]=0.f; }
        if (l31) { hh[0]=0.f; hh[1]=0.f; hh[2]=0.f; hh[3]=0.f; hh[4]=0.f; }

        // adjacent pairs over extended segment e[0..15]
        u64 P[15];
        P[0]  = pk(hl[0], hl[1]);
        P[1]  = pk(hl[1], hl[2]);
        P[2]  = pk(hl[2], hl[3]);
        P[3]  = pk(hl[3], hl[4]);
        P[4]  = pk(hl[4], cur[0]);
        P[5]  = pk(cur[0], cur[1]);
        P[6]  = pk(cur[1], cur[2]);
        P[7]  = pk(cur[2], cur[3]);
        P[8]  = pk(cur[3], cur[4]);
        P[9]  = pk(cur[4], cur[5]);
        P[10] = pk(cur[5], hh[0]);
        P[11] = pk(hh[0], hh[1]);
        P[12] = pk(hh[1], hh[2]);
        P[13] = pk(hh[2], hh[3]);
        P[14] = pk(hh[3], hh[4]);

        // horizontal blur (packed, even/odd split chains)
        u64 h2[3];
#pragma unroll
        for (int j = 0; j < 3; ++j) {
            u64 sa = f2mul(P[2*j + 0], w2[5]);
            sa = f2fma(P[2*j + 2],  w2[3], sa);
            sa = f2fma(P[2*j + 4],  w2[1], sa);
            sa = f2fma(P[2*j + 6],  w2[1], sa);
            sa = f2fma(P[2*j + 8],  w2[3], sa);
            sa = f2fma(P[2*j + 10], w2[5], sa);
            u64 sb2 = f2mul(P[2*j + 1], w2[4]);
            sb2 = f2fma(P[2*j + 3],  w2[2], sb2);
            sb2 = f2fma(P[2*j + 5],  w2[0], sb2);
            sb2 = f2fma(P[2*j + 7],  w2[2], sb2);
            sb2 = f2fma(P[2*j + 9],  w2[4], sb2);
            h2[j] = f2add(sa, sb2);
        }

        // vertical taps: k=0..9 accumulate, k=10 overwrites recycled slot
#pragma unroll
        for (int k = 0; k < 10; ++k) {
            const u64 wv = w2[k <= 5 ? 5 - k : k - 5];
            const int s = (U + k) % 11;
            acc[s][0] = f2fma(h2[0], wv, acc[s][0]);
            acc[s][1] = f2fma(h2[1], wv, acc[s][1]);
            acc[s][2] = f2fma(h2[2], wv, acc[s][2]);
        }
        {
            const int s = (U + 10) % 11;
            acc[s][0] = f2mul(h2[0], w2[5]);
            acc[s][1] = f2mul(h2[1], w2[5]);
            acc[s][2] = f2mul(h2[2], w2[5]);
        }
    } else {
        const int s = (U + 10) % 11;
        acc[s][0] = 0ull; acc[s][1] = 0ull; acc[s][2] = 0ull;
    }

    if (EMIT) {
        float a0, a1, a2, a3, a4, a5;
        upk(acc[U][0], a0, a1);
        upk(acc[U][1], a2, a3);
        upk(acc[U][2], a4, a5);
        const float m01 = fmaxf(a0, a1);
        const float m23 = fmaxf(a2, a3);
        const float m45 = fmaxf(a4, a5);
        const float rowmax = fmaxf(fmaxf(m01, m23), m45);
        if (rowmax > bestv) {        // rare
            bestv = rowmax;
            int c = 5;
            if (a4 == rowmax) c = 4;
            if (a3 == rowmax) c = 3;
            if (a2 == rowmax) c = 2;
            if (a1 == rowmax) c = 1;
            if (a0 == rowmax) c = 0;
            bestlin = ebl + U * IW + c;
        }
    }

#pragma unroll
    for (int c = 0; c < 6; ++c) cur[c] = nc[c];
}

// One CTA (64 threads = 2 warps) per (b,k) image; warp w owns output rows
// [w*128, w*128+128), lane owns 6 columns. Head (11 guarded, direct LDG) +
// main (11x11 branch-free, cp.async smem ring, distance 6) + tail (6 guarded).
__global__ __launch_bounds__(64, 8)
void dark_decode_kernel(const float* __restrict__ hm,
                        float* __restrict__ out, int n_img)
{
    const int img  = blockIdx.x;
    const int warp = threadIdx.x >> 5;
    const int lane = threadIdx.x & 31;
    const float* __restrict__ ip = hm + (long long)img * (IH * IW);
    const int base = warp * 128;
    const int col0 = lane * 6;
    const bool l0  = (lane == 0);
    const bool l31 = (lane == 31);

    // per-warp 8-row ring (rows padded to 1KB), lane owns 24B per row
    __shared__ __align__(16) char ring[2 * 8192];
    const u32 sb = smem_u32(ring) + warp * 8192 + lane * 24;

    u64 w2[6];
#pragma unroll
    for (int k = 0; k < 6; ++k) w2[k] = pk(wt(k), wt(k));

    u64 acc[11][3];   // no init needed: every slot is overwritten before emit

    // ---- prologue: start cp.async pipeline with rows base+7 .. base+12 ----
    u32 wro = 0;
    const float* gp = ip + (base + 7) * IW + col0;
#pragma unroll
    for (int j = 0; j < 6; ++j) {
        const u32 wr = sb + wro;
        CP_ASYNC8(wr,       gp);
        CP_ASYNC8(wr + 8u,  gp + 2);
        CP_ASYNC8(wr + 16u, gp + 4);
        CP_COMMIT();
        wro = (wro + 1024u) & 8191u;
        gp += IW;
    }

    float cur[6];
    {   // row base-5 (warp0: OOB -> zeros)
        const int r0 = base - 5;
        if (r0 >= 0) {
            const float* p = ip + r0 * IW + col0;
            float2 a = *(const float2*)p;
            float2 b = *(const float2*)(p + 2);
            float2 c = *(const float2*)(p + 4);
            cur[0]=a.x; cur[1]=a.y; cur[2]=b.x; cur[3]=b.y; cur[4]=c.x; cur[5]=c.y;
        } else {
#pragma unroll
            for (int c = 0; c < 6; ++c) cur[c] = 0.f;
        }
    }

    float bestv   = -3.4e38f;
    int   bestlin = 0;

    // ---- head: i = 0..10 (r = base-5+i), guarded LDG; emit only at i=10 ----
    {
        const int eblh = (base - 10) * IW + col0;
#define HSTEP(U, EM) step<U, false, EM, false>(ip, base - 5 + (U), col0, cur, \
                        acc, w2, l0, l31, bestv, bestlin, eblh, sb, wro, gp)
        HSTEP(0, false); HSTEP(1, false); HSTEP(2, false); HSTEP(3, false);
        HSTEP(4, false); HSTEP(5, false); HSTEP(6, false); HSTEP(7, false);
        HSTEP(8, false); HSTEP(9, false); HSTEP(10, true);
#undef HSTEP
    }

    // ---- main: i = 11..131, 11 blocks x 11 steps, smem ring ----
    // step m (= i-11) consumes smem row base+7+m; prefetches row base+13+m.
    {
        int ebl = (base + 1) * IW + col0;   // ro at ib=0,U=0
#define MSTEP(U, PF) step<U, true, true, PF>(ip, 0, col0, cur, acc, w2, \
                        l0, l31, bestv, bestlin, ebl, sb, wro, gp)
        for (int ib = 0; ib < 10; ++ib) {   // blocks 0..9: prefetch always on
            MSTEP(0, true); MSTEP(1, true); MSTEP(2, true); MSTEP(3, true);
            MSTEP(4, true); MSTEP(5, true); MSTEP(6, true); MSTEP(7, true);
            MSTEP(8, true); MSTEP(9, true); MSTEP(10, true);
            ebl += 11 * IW;
        }
        // block 10 (m = 110..120): prefetch only while m <= 114 (U <= 4)
        MSTEP(0, true);  MSTEP(1, true);  MSTEP(2, true);  MSTEP(3, true);
        MSTEP(4, true);  MSTEP(5, false); MSTEP(6, false); MSTEP(7, false);
        MSTEP(8, false); MSTEP(9, false); MSTEP(10, false);
#undef MSTEP
        CP_WAIT(0);   // drain pipeline before exit paths
    }

    // ---- tail: i = 132..137 (U = 0..5), guarded LDG, always emit ----
    {
        const int eblt = (base + 122) * IW + col0;
#define TSTEP(U) step<U, false, true, false>(ip, base + 127 + (U), col0, cur, \
                        acc, w2, l0, l31, bestv, bestlin, eblt, sb, wro, gp)
        TSTEP(0); TSTEP(1); TSTEP(2); TSTEP(3); TSTEP(4); TSTEP(5);
#undef TSTEP
    }

    // intra-warp argmax reduce (larger value wins; tie -> smaller linear index)
#pragma unroll
    for (int off = 16; off >= 1; off >>= 1) {
        const float ov = __shfl_xor_sync(FULLMASK, bestv, off);
        const int   oi = __shfl_xor_sync(FULLMASK, bestlin, off);
        if (ov > bestv || (ov == bestv && oi < bestlin)) { bestv = ov; bestlin = oi; }
    }

    __shared__ float s_v[2];
    __shared__ int   s_i[2];
    if (lane == 0) { s_v[warp] = bestv; s_i[warp] = bestlin; }
    __syncthreads();
    if (warp != 0) return;

    float fv; int fl;
    {
        const float v0 = s_v[0], v1 = s_v[1];
        const int   i0 = s_i[0], i1 = s_i[1];
        if (v1 > v0 || (v1 == v0 && i1 < i0)) { fv = v1; fl = i1; }
        else                                  { fv = v0; fl = i0; }
    }
    const int py = fl / IW;
    const int px = fl - py * IW;

    float offx = 0.f, offy = 0.f;
    const bool bok = (px >= 1) && (px < IW - 1) && (py >= 1) && (py < IH - 1);
    if (bok) {
        // 39 hblur values: flat j in [0,39), rr = py-6 + j/3, cc = px-1 + j%3
        float h0 = 0.f, h1 = 0.f;
        {
            int j = lane;
            int rr = py - 6 + j / 3;
            int cc = px - 1 + (j - (j / 3) * 3);
            if (rr >= 0 && rr < IH) {
                const float* rp2 = ip + rr * IW;
                float s = 0.f;
#pragma unroll
                for (int d = -5; d <= 5; ++d) {
                    const int c = cc + d;
                    float v = 0.f;
                    if ((unsigned)c < (unsigned)IW) v = rp2[c];
                    s += v * wt(d < 0 ? -d : d);
                }
                h0 = s;
            }
            j = lane + 32;
            if (j < 39) {
                rr = py - 6 + j / 3;
                cc = px - 1 + (j - (j / 3) * 3);
                if (rr >= 0 && rr < IH) {
                    const float* rp2 = ip + rr * IW;
                    float s = 0.f;
#pragma unroll
                    for (int d = -5; d <= 5; ++d) {
                        const int c = cc + d;
                        float v = 0.f;
                        if ((unsigned)c < (unsigned)IW) v = rp2[c];
                        s += v * wt(d < 0 ? -d : d);
                    }
                    h1 = s;
                }
            }
        }
        // lanes 0..8: vertical blur -> patch entry p(a,b), a=lane/3, b=lane%3
        const int a = lane / 3;
        const int b = lane - a * 3;
        float p = 0.f;
#pragma unroll
        for (int t = 0; t < 11; ++t) {
            const int j = (a + t) * 3 + b;
            const float va = __shfl_sync(FULLMASK, h0, j & 31);
            const float vb = __shfl_sync(FULLMASK, h1, j & 31);
            const float hv = (j < 32) ? va : vb;
            p += hv * wt(t <= 5 ? 5 - t : t - 5);
        }
        const float p00 = __shfl_sync(FULLMASK, p, 0);
        const float p01 = __shfl_sync(FULLMASK, p, 1);
        const float p02 = __shfl_sync(FULLMASK, p, 2);
        const float p10 = __shfl_sync(FULLMASK, p, 3);
        const float p11 = __shfl_sync(FULLMASK, p, 4);
        const float p12 = __shfl_sync(FULLMASK, p, 5);
        const float p20 = __shfl_sync(FULLMASK, p, 6);
        const float p21 = __shfl_sync(FULLMASK, p, 7);
        const float p22 = __shfl_sync(FULLMASK, p, 8);

        const float dx  = (p12 - p10) * 0.5f;
        const float dy  = (p21 - p01) * 0.5f;
        const float dxx = p12 - 2.f * p11 + p10;
        const float dyy = p21 - 2.f * p11 + p01;
        const float dxy = (p22 - p20 - p02 + p00) * 0.25f;
        const float det = dxx * dyy - dxy * dxy;
        if (fabsf(det) >= 1e-6f && dxx < 0.f) {
            const float ox = -(dyy * dx - dxy * dy) / det;
            const float oy = -(dxx * dy - dxy * dx) / det;
            offx = fminf(fmaxf(ox, -0.5f), 0.5f);
            offy = fminf(fmaxf(oy, -0.5f), 0.5f);
        }
    }

    if (lane == 0) {
        const float xo = fminf(fmaxf((float)px + offx, 0.f), (float)(IW - 1));
        const float yo = fminf(fmaxf((float)py + offy, 0.f), (float)(IH - 1));
        out[2 * img + 0] = xo;                       // coords[...,0] = x
        out[2 * img + 1] = yo;                       // coords[...,1] = y
        out[(long long)2 * n_img + img] = fv;        // max_vals
    }
}

extern "C" void kernel_launch(void* const* d_in, const int* in_sizes, int n_in,
                              void* d_out, int out_size)
{
    const float* hm = (const float*)d_in[0];
    // d_in[1] is kernel_size (always 11 in this problem; taps are baked in)
    const int n_img = in_sizes[0] / (IH * IW);
    dark_decode_kernel<<<n_img, 64>>>(hm, (float*)d_out, n_img);
}

// round 10
// speedup vs baseline: 1.2523x; 1.0448x over previous
#include <cuda_runtime.h>

#define FULLMASK 0xffffffffu
#define IH 256
#define IW 192

typedef unsigned long long u64;

// Gaussian taps for kernel_size=11, sigma=10/6, normalized. Indexed by |d|.
static __device__ __forceinline__ float wt(int k) {
    const float t[6] = {0.23955940f, 0.20009682f, 0.11660614f,
                        0.04740849f, 0.01344761f, 0.00266126f};
    return t[k];
}

static __device__ __forceinline__ u64 pk(float lo, float hi) {
    u64 r; asm("mov.b64 %0, {%1, %2};" : "=l"(r) : "f"(lo), "f"(hi)); return r;
}
static __device__ __forceinline__ void upk(u64 v, float& lo, float& hi) {
    asm("mov.b64 {%0, %1}, %2;" : "=f"(lo), "=f"(hi) : "l"(v));
}
static __device__ __forceinline__ u64 f2mul(u64 a, u64 b) {
    u64 d; asm("mul.rn.f32x2 %0, %1, %2;" : "=l"(d) : "l"(a), "l"(b)); return d;
}
static __device__ __forceinline__ u64 f2fma(u64 a, u64 b, u64 c) {
    u64 d; asm("fma.rn.f32x2 %0, %1, %2, %3;" : "=l"(d) : "l"(a), "l"(b), "l"(c)); return d;
}
static __device__ __forceinline__ u64 f2add(u64 a, u64 b) {
    u64 d; asm("add.rn.f32x2 %0, %1, %2;" : "=l"(d) : "l"(a), "l"(b)); return d;
}

// One step of the fused blur/argmax pipeline (prefetch distance 1).
//  U      : static slot phase (i mod 11)
//  GUARD  : head/tail mode — runtime row/load bounds checks (warp-uniform)
//  EMIT   : fold completed output row (slot U) into branchless running max
// cur holds row r; this step consumes it and loads row r+1 into cur.
template<int U, bool GUARD, bool EMIT>
static __device__ __forceinline__ void step(
    const float* __restrict__ rp,   // main-mode load base: row of U=0 load
    const float* __restrict__ ip,   // image base (GUARD-mode addressing)
    int r, int col0,
    float (&cur)[6], u64 (&acc)[11][3], const u64 (&w2)[6],
    bool l0, bool l31, float& bestv, int& bestrow, int ebl)
{
    // ---- load row r+1 ----
    float nc[6];
    bool loadok = true, rowok = true;
    if (GUARD) {
        loadok = ((unsigned)(r + 1) < (unsigned)IH);
        rowok  = ((unsigned)r       < (unsigned)IH);
    }
    if (loadok) {
        const float* p = GUARD ? (ip + (r + 1) * IW + col0) : (rp + U * IW);
        float2 a = *(const float2*)p;
        float2 b = *(const float2*)(p + 2);
        float2 c = *(const float2*)(p + 4);
        nc[0] = a.x; nc[1] = a.y; nc[2] = b.x;
        nc[3] = b.y; nc[4] = c.x; nc[5] = c.y;
    } else {
        nc[0] = nc[1] = nc[2] = nc[3] = nc[4] = nc[5] = 0.f;
    }

    if (rowok) {
        // halos: lo = cols col0-5..col0-1, hi = cols col0+6..col0+10
        float hl[5], hh[5];
        hl[0] = __shfl_up_sync(FULLMASK, cur[1], 1);
        hl[1] = __shfl_up_sync(FULLMASK, cur[2], 1);
        hl[2] = __shfl_up_sync(FULLMASK, cur[3], 1);
        hl[3] = __shfl_up_sync(FULLMASK, cur[4], 1);
        hl[4] = __shfl_up_sync(FULLMASK, cur[5], 1);
        hh[0] = __shfl_down_sync(FULLMASK, cur[0], 1);
        hh[1] = __shfl_down_sync(FULLMASK, cur[1], 1);
        hh[2] = __shfl_down_sync(FULLMASK, cur[2], 1);
        hh[3] = __shfl_down_sync(FULLMASK, cur[3], 1);
        hh[4] = __shfl_down_sync(FULLMASK, cur[4], 1);
        if (l0)  { hl[0]=0.f; hl[1]=0.f; hl[2]=0.f; hl[3]=0.f; hl[4]=0.f; }
        if (l31) { hh[0]=0.f; hh[1]=0.f; hh[2]=0.f; hh[3]=0.f; hh[4]=0.f; }

        // adjacent pairs over extended segment e[0..15]
        u64 P[15];
        P[0]  = pk(hl[0], hl[1]);
        P[1]  = pk(hl[1], hl[2]);
        P[2]  = pk(hl[2], hl[3]);
        P[3]  = pk(hl[3], hl[4]);
        P[4]  = pk(hl[4], cur[0]);
        P[5]  = pk(cur[0], cur[1]);
        P[6]  = pk(cur[1], cur[2]);
        P[7]  = pk(cur[2], cur[3]);
        P[8]  = pk(cur[3], cur[4]);
        P[9]  = pk(cur[4], cur[5]);
        P[10] = pk(cur[5], hh[0]);
        P[11] = pk(hh[0], hh[1]);
        P[12] = pk(hh[1], hh[2]);
        P[13] = pk(hh[2], hh[3]);
        P[14] = pk(hh[3], hh[4]);

        // horizontal blur (packed, even/odd split chains)
        u64 h2[3];
#pragma unroll
        for (int j = 0; j < 3; ++j) {
            u64 sa = f2mul(P[2*j + 0], w2[5]);
            sa = f2fma(P[2*j + 2],  w2[3], sa);
            sa = f2fma(P[2*j + 4],  w2[1], sa);
            sa = f2fma(P[2*j + 6],  w2[1], sa);
            sa = f2fma(P[2*j + 8],  w2[3], sa);
            sa = f2fma(P[2*j + 10], w2[5], sa);
            u64 sb = f2mul(P[2*j + 1], w2[4]);
            sb = f2fma(P[2*j + 3],  w2[2], sb);
            sb = f2fma(P[2*j + 5],  w2[0], sb);
            sb = f2fma(P[2*j + 7],  w2[2], sb);
            sb = f2fma(P[2*j + 9],  w2[4], sb);
            h2[j] = f2add(sa, sb);
        }

        // vertical taps: k=0..9 accumulate, k=10 overwrites recycled slot
#pragma unroll
        for (int k = 0; k < 10; ++k) {
            const u64 wv = w2[k <= 5 ? 5 - k : k - 5];
            const int s = (U + k) % 11;
            acc[s][0] = f2fma(h2[0], wv, acc[s][0]);
            acc[s][1] = f2fma(h2[1], wv, acc[s][1]);
            acc[s][2] = f2fma(h2[2], wv, acc[s][2]);
        }
        {
            const int s = (U + 10) % 11;
            acc[s][0] = f2mul(h2[0], w2[5]);
            acc[s][1] = f2mul(h2[1], w2[5]);
            acc[s][2] = f2mul(h2[2], w2[5]);
        }
    } else {
        const int s = (U + 10) % 11;
        acc[s][0] = 0ull; acc[s][1] = 0ull; acc[s][2] = 0ull;
    }

    if (EMIT) {
        float a0, a1, a2, a3, a4, a5;
        upk(acc[U][0], a0, a1);
        upk(acc[U][1], a2, a3);
        upk(acc[U][2], a4, a5);
        const float m01 = fmaxf(a0, a1);
        const float m23 = fmaxf(a2, a3);
        const float m45 = fmaxf(a4, a5);
        const float rowmax = fmaxf(fmaxf(m01, m23), m45);
        // branchless: keep max value; row-base updates only on strict improve
        // (ties keep the earlier row, matching first-argmax semantics).
        const int rowbase = ebl + U * IW;        // ro*IW + col0
        bestrow = (rowmax > bestv) ? rowbase : bestrow;
        bestv   = fmaxf(bestv, rowmax);
    }

#pragma unroll
    for (int c = 0; c < 6; ++c) cur[c] = nc[c];
}

// One CTA (64 threads = 2 warps) per (b,k) image; warp w owns output rows
// [w*128, w*128+128), lane owns 6 columns. Head (11 guarded) + main
// (11x11 branch-free) + tail (6 guarded). Weights live in registers.
__global__ __launch_bounds__(64, 8)
void dark_decode_kernel(const float* __restrict__ hm,
                        float* __restrict__ out, int n_img)
{
    const int img  = blockIdx.x;
    const int warp = threadIdx.x >> 5;
    const int lane = threadIdx.x & 31;
    const float* __restrict__ ip = hm + (long long)img * (IH * IW);
    const int base = warp * 128;
    const int col0 = lane * 6;
    const bool l0  = (lane == 0);
    const bool l31 = (lane == 31);

    u64 w2[6];
#pragma unroll
    for (int k = 0; k < 6; ++k) w2[k] = pk(wt(k), wt(k));

    u64 acc[11][3];   // no init needed: every slot is overwritten before emit

    float cur[6];
    {   // row base-5 (warp0: OOB -> zeros)
        const int r0 = base - 5;
        if (r0 >= 0) {
            const float* p = ip + r0 * IW + col0;
            float2 a = *(const float2*)p;
            float2 b = *(const float2*)(p + 2);
            float2 c = *(const float2*)(p + 4);
            cur[0]=a.x; cur[1]=a.y; cur[2]=b.x; cur[3]=b.y; cur[4]=c.x; cur[5]=c.y;
        } else {
#pragma unroll
            for (int c = 0; c < 6; ++c) cur[c] = 0.f;
        }
    }

    float bestv   = -3.4e38f;
    int   bestrow = 0;

    // ---- head: i = 0..10 (r = base-5+i), guarded; emit only at i=10 ----
    {
        const int eblh = (base - 10) * IW + col0;
#define HSTEP(U, EM) step<U, true, EM>(ip, ip, base - 5 + (U), col0, cur, acc, \
                                       w2, l0, l31, bestv, bestrow, eblh)
        HSTEP(0, false); HSTEP(1, false); HSTEP(2, false); HSTEP(3, false);
        HSTEP(4, false); HSTEP(5, false); HSTEP(6, false); HSTEP(7, false);
        HSTEP(8, false); HSTEP(9, false); HSTEP(10, true);
#undef HSTEP
    }

    // ---- main: i = 11..131, 11 blocks x 11 steps, branch-free ----
    {
        const float* rp = ip + (base + 7) * IW + col0;   // row r+1 at ib=0,U=0
        int ebl = (base + 1) * IW + col0;                // ro at ib=0,U=0
#define MSTEP(U) step<U, false, true>(rp, ip, 0, col0, cur, acc, w2, l0, l31, \
                                      bestv, bestrow, ebl)
        for (int ib = 0; ib < 11; ++ib) {
            MSTEP(0); MSTEP(1); MSTEP(2); MSTEP(3); MSTEP(4); MSTEP(5);
            MSTEP(6); MSTEP(7); MSTEP(8); MSTEP(9); MSTEP(10);
            rp  += 11 * IW;
            ebl += 11 * IW;
        }
#undef MSTEP
    }

    // ---- tail: i = 132..137 (U = 0..5), guarded, always emit ----
    {
        const int eblt = (base + 122) * IW + col0;
#define TSTEP(U) step<U, true, true>(ip, ip, base + 127 + (U), col0, cur, acc, \
                                     w2, l0, l31, bestv, bestrow, eblt)
        TSTEP(0); TSTEP(1); TSTEP(2); TSTEP(3); TSTEP(4); TSTEP(5);
#undef TSTEP
    }

    // intra-warp argmax reduce (larger value wins; tie -> smaller row-base,
    // which equals smaller linear index since col is recovered later)
#pragma unroll
    for (int off = 16; off >= 1; off >>= 1) {
        const float ov = __shfl_xor_sync(FULLMASK, bestv, off);
        const int   oi = __shfl_xor_sync(FULLMASK, bestrow, off);
        if (ov > bestv || (ov == bestv && oi < bestrow)) { bestv = ov; bestrow = oi; }
    }

    __shared__ float s_v[2];
    __shared__ int   s_i[2];
    if (lane == 0) { s_v[warp] = bestv; s_i[warp] = bestrow; }
    __syncthreads();
    if (warp != 0) return;

    float fv; int fl;
    {
        const float v0 = s_v[0], v1 = s_v[1];
        const int   i0 = s_i[0], i1 = s_i[1];
        if (v1 > v0 || (v1 == v0 && i1 < i0)) { fv = v1; fl = i1; }
        else                                  { fv = v0; fl = i0; }
    }
    const int py  = fl / IW;
    const int c0w = fl - py * IW;     // winning lane's col0

    // ---- column recovery: lanes 0..5 recompute blurred(py, c0w+lane)
    // bitwise-identically to the streaming accumulation (same chains/order).
    float val = -3.4e38f;
    if (lane < 6) {
        const int cc = c0w + lane;
        val = 0.f;
#pragma unroll
        for (int t = 0; t < 11; ++t) {
            const int r = py - 5 + t;
            if (r >= 0 && r < IH) {
                const float* rp2 = ip + r * IW;
                float x[11];
#pragma unroll
                for (int d = -5; d <= 5; ++d) {
                    const int c = cc + d;
                    x[d + 5] = ((unsigned)c < (unsigned)IW) ? rp2[c] : 0.f;
                }
                float sa = x[0] * wt(5);          // dist -5
                sa = fmaf(x[2],  wt(3), sa);      // -3
                sa = fmaf(x[4],  wt(1), sa);      // -1
                sa = fmaf(x[6],  wt(1), sa);      // +1
                sa = fmaf(x[8],  wt(3), sa);      // +3
                sa = fmaf(x[10], wt(5), sa);      // +5
                float sb = x[1] * wt(4);          // -4
                sb = fmaf(x[3], wt(2), sb);       // -2
                sb = fmaf(x[5], wt(0), sb);       //  0
                sb = fmaf(x[7], wt(2), sb);       // +2
                sb = fmaf(x[9], wt(4), sb);       // +4
                const float h = sa + sb;
                val = fmaf(h, wt(t < 5 ? 5 - t : t - 5), val);
            }
        }
    }
    // first-max among lanes 0..5 (8-lane bfly max + ballot + ffs)
    float mx = val;
    mx = fmaxf(mx, __shfl_xor_sync(FULLMASK, mx, 1));
    mx = fmaxf(mx, __shfl_xor_sync(FULLMASK, mx, 2));
    mx = fmaxf(mx, __shfl_xor_sync(FULLMASK, mx, 4));
    const unsigned bal = __ballot_sync(FULLMASK, (lane < 6) && (val == mx));
    const int cwin = __ffs(bal) - 1;
    const int px = c0w + cwin;

    float offx = 0.f, offy = 0.f;
    const bool bok = (px >= 1) && (px < IW - 1) && (py >= 1) && (py < IH - 1);
    if (bok) {
        // 39 hblur values: flat j in [0,39), rr = py-6 + j/3, cc = px-1 + j%3
        float h0 = 0.f, h1 = 0.f;
        {
            int j = lane;
            int rr = py - 6 + j / 3;
            int cc = px - 1 + (j - (j / 3) * 3);
            if (rr >= 0 && rr < IH) {
                const float* rp2 = ip + rr * IW;
                float s = 0.f;
#pragma unroll
                for (int d = -5; d <= 5; ++d) {
                    const int c = cc + d;
                    float v = 0.f;
                    if ((unsigned)c < (unsigned)IW) v = rp2[c];
                    s += v * wt(d < 0 ? -d : d);
                }
                h0 = s;
            }
            j = lane + 32;
            if (j < 39) {
                rr = py - 6 + j / 3;
                cc = px - 1 + (j - (j / 3) * 3);
                if (rr >= 0 && rr < IH) {
                    const float* rp2 = ip + rr * IW;
                    float s = 0.f;
#pragma unroll
                    for (int d = -5; d <= 5; ++d) {
                        const int c = cc + d;
                        float v = 0.f;
                        if ((unsigned)c < (unsigned)IW) v = rp2[c];
                        s += v * wt(d < 0 ? -d : d);
                    }
                    h1 = s;
                }
            }
        }
        // lanes 0..8: vertical blur -> patch entry p(a,b), a=lane/3, b=lane%3
        const int a = lane / 3;
        const int b = lane - a * 3;
        float p = 0.f;
#pragma unroll
        for (int t = 0; t < 11; ++t) {
            const int j = (a + t) * 3 + b;
            const float va = __shfl_sync(FULLMASK, h0, j & 31);
            const float vb = __shfl_sync(FULLMASK, h1, j & 31);
            const float hv = (j < 32) ? va : vb;
            p += hv * wt(t <= 5 ? 5 - t : t - 5);
        }
        const float p00 = __shfl_sync(FULLMASK, p, 0);
        const float p01 = __shfl_sync(FULLMASK, p, 1);
        const float p02 = __shfl_sync(FULLMASK, p, 2);
        const float p10 = __shfl_sync(FULLMASK, p, 3);
        const float p11 = __shfl_sync(FULLMASK, p, 4);
        const float p12 = __shfl_sync(FULLMASK, p, 5);
        const float p20 = __shfl_sync(FULLMASK, p, 6);
        const float p21 = __shfl_sync(FULLMASK, p, 7);
        const float p22 = __shfl_sync(FULLMASK, p, 8);

        const float dx  = (p12 - p10) * 0.5f;
        const float dy  = (p21 - p01) * 0.5f;
        const float dxx = p12 - 2.f * p11 + p10;
        const float dyy = p21 - 2.f * p11 + p01;
        const float dxy = (p22 - p20 - p02 + p00) * 0.25f;
        const float det = dxx * dyy - dxy * dxy;
        if (fabsf(det) >= 1e-6f && dxx < 0.f) {
            const float ox = -(dyy * dx - dxy * dy) / det;
            const float oy = -(dxx * dy - dxy * dx) / det;
            offx = fminf(fmaxf(ox, -0.5f), 0.5f);
            offy = fminf(fmaxf(oy, -0.5f), 0.5f);
        }
    }

    if (lane == 0) {
        const float xo = fminf(fmaxf((float)px + offx, 0.f), (float)(IW - 1));
        const float yo = fminf(fmaxf((float)py + offy, 0.f), (float)(IH - 1));
        out[2 * img + 0] = xo;                       // coords[...,0] = x
        out[2 * img + 1] = yo;                       // coords[...,1] = y
        out[(long long)2 * n_img + img] = fv;        // max_vals
    }
}

extern "C" void kernel_launch(void* const* d_in, const int* in_sizes, int n_in,
                              void* d_out, int out_size)
{
    const float* hm = (const float*)d_in[0];
    // d_in[1] is kernel_size (always 11 in this problem; taps are baked in)
    const int n_img = in_sizes[0] / (IH * IW);
    dark_decode_kernel<<<n_img, 64>>>(hm, (float*)d_out, n_img);
}